// round 8
// baseline (speedup 1.0000x reference)
#include <cuda_runtime.h>

#define NQ        8
#define BINS      256
#define DIM       128
#define NROWS     8192
#define MROWS     64
#define NTHREADS  512
#define NCTAS     (NROWS / MROWS)   // 128
#define RES_PITCH 132               // floats per residual/quant row (bank-conflict-free float4)
#define MARGIN    0.03f

// ---- shared memory layout (float offsets) ----
#define OFF_CB    0                              // 256*128 = 32768
#define OFF_RES   (OFF_CB + BINS * DIM)          // 32768
#define OFF_Q     (OFF_RES + MROWS * RES_PITCH)  // 41216
#define OFF_NORM  (OFF_Q + MROWS * RES_PITCH)    // 49664
#define OFF_RM1   (OFF_NORM + BINS)              // 49920 : per-warp best   [16][64]
#define OFF_RI1   (OFF_RM1 + 16 * MROWS)         // 50944 : per-warp bestidx[16][64] (int)
#define OFF_RM2   (OFF_RI1 + 16 * MROWS)         // 51968 : per-warp 2nd    [16][64]
#define OFF_BEST  (OFF_RM2 + 16 * MROWS)         // 52992 : final idx [64] (int)
#define OFF_FLAG  (OFF_BEST + MROWS)             // 53056 : near-tie flag [64] (int)
#define SMEM_FLOATS (OFF_FLAG + MROWS)           // 53120
#define SMEM_BYTES  (SMEM_FLOATS * 4)            // 212480 bytes

// packed fp32x2 FMA: d.lo += a.lo*b.lo ; d.hi += a.hi*b.hi   (sm_103a FFMA2)
__device__ __forceinline__ void ffma2(unsigned long long& d,
                                      unsigned long long a,
                                      unsigned long long b) {
    asm volatile("fma.rn.f32x2 %0, %1, %2, %0;" : "+l"(d) : "l"(a), "l"(b));
}

__device__ __forceinline__ float pk_lo(unsigned long long v) {
    return __uint_as_float((unsigned)(v & 0xffffffffULL));
}
__device__ __forceinline__ float pk_hi(unsigned long long v) {
    return __uint_as_float((unsigned)(v >> 32));
}

// async copy of one 128KB codebook level into smem; one commit group
__device__ __forceinline__ void load_cb_async(float* dst, const float* src, int tid) {
    unsigned base = (unsigned)__cvta_generic_to_shared(dst);
    const char* s = (const char*)src;
#pragma unroll
    for (int i = 0; i < 16; ++i) {
        int off = (i * NTHREADS + tid) * 16;
        asm volatile("cp.async.cg.shared.global [%0], [%1], 16;\n"
                     :: "r"(base + off), "l"(s + off));
    }
    asm volatile("cp.async.commit_group;\n");
}
__device__ __forceinline__ void cp_wait_all() {
    asm volatile("cp.async.wait_group 0;\n" ::: "memory");
}

__global__ void __launch_bounds__(NTHREADS, 1)
rvq_kernel(const float* __restrict__ hidden,
           const float* __restrict__ cbg,
           float* __restrict__ codes_out,   // may be null
           float* __restrict__ q_out)       // may be null
{
    extern __shared__ float smem[];
    float* scb   = smem + OFF_CB;
    float* sres  = smem + OFF_RES;
    float* sq    = smem + OFF_Q;
    float* snorm = smem + OFF_NORM;
    float* rm1   = smem + OFF_RM1;
    int*   ri1   = (int*)(smem + OFF_RI1);
    float* rm2   = smem + OFF_RM2;
    int*   sbest = (int*)(smem + OFF_BEST);
    int*   sflag = (int*)(smem + OFF_FLAG);

    const int tid  = threadIdx.x;
    const int lane = tid & 31;
    const int w    = tid >> 5;                  // 0..15
    const int rowbase = blockIdx.x * MROWS;
    const float INF = __int_as_float(0x7f800000);

    // prefetch level-0 codebook
    load_cb_async(scb, cbg, tid);

    // residual := hidden rows; quantized := 0
    for (int idx = tid; idx < MROWS * (DIM / 4); idx += NTHREADS) {
        int row = idx >> 5;
        int kq  = idx & 31;
        float4 v = *(const float4*)(hidden + (size_t)(rowbase + row) * DIM + kq * 4);
        *(float4*)(sres + row * RES_PITCH + kq * 4) = v;
        *(float4*)(sq   + row * RES_PITCH + kq * 4) = make_float4(0.f, 0.f, 0.f, 0.f);
    }
    cp_wait_all();
    __syncthreads();

    for (int lev = 0; lev < NQ; ++lev) {
        // ---- codebook entry norms (2 threads per entry) ----
        {
            int e = tid >> 1, h = tid & 1;
            const float* cp = scb + e * DIM + h * 64;
            float s = 0.f;
#pragma unroll
            for (int k = 0; k < 64; k += 4) {
                float4 v = *(const float4*)(cp + k);
                s = fmaf(v.x, v.x, s); s = fmaf(v.y, v.y, s);
                s = fmaf(v.z, v.z, s); s = fmaf(v.w, v.w, s);
            }
            s += __shfl_xor_sync(0xffffffffu, s, 1);
            if (h == 0) snorm[e] = s;
        }
        __syncthreads();

        // ---- main scoring: warp w handles entries [16w,16w+16), lane handles rows lane & lane+32 ----
        float m1a = INF, m2a = INF; int i1a = 0;   // row lane
        float m1b = INF, m2b = INF; int i1b = 0;   // row lane+32
        const float* rp0 = sres + lane * RES_PITCH;
        const float* rp1 = rp0 + 32 * RES_PITCH;

        for (int pass = 0; pass < 2; ++pass) {
            const int ebase = w * 16 + pass * 8;
            const float* cp = scb + ebase * DIM;
            unsigned long long acc0[8], acc1[8];
#pragma unroll
            for (int e = 0; e < 8; ++e) { acc0[e] = 0ull; acc1[e] = 0ull; }

#pragma unroll 4
            for (int kq = 0; kq < 32; ++kq) {
                ulonglong2 a0 = *(const ulonglong2*)(rp0 + kq * 4);
                ulonglong2 a1 = *(const ulonglong2*)(rp1 + kq * 4);
#pragma unroll
                for (int e = 0; e < 8; ++e) {
                    ulonglong2 b = *(const ulonglong2*)(cp + e * DIM + kq * 4);
                    ffma2(acc0[e], a0.x, b.x);
                    ffma2(acc0[e], a0.y, b.y);
                    ffma2(acc1[e], a1.x, b.x);
                    ffma2(acc1[e], a1.y, b.y);
                }
            }
#pragma unroll
            for (int e = 0; e < 8; ++e) {
                int eg = ebase + e;
                float n = snorm[eg];
                float d0 = pk_lo(acc0[e]) + pk_hi(acc0[e]);
                float d1 = pk_lo(acc1[e]) + pk_hi(acc1[e]);
                float s0 = fmaf(-2.f, d0, n);
                float s1 = fmaf(-2.f, d1, n);
                if (s0 < m1a) { m2a = m1a; m1a = s0; i1a = eg; }
                else if (s0 < m2a) { m2a = s0; }
                if (s1 < m1b) { m2b = m1b; m1b = s1; i1b = eg; }
                else if (s1 < m2b) { m2b = s1; }
            }
        }
        rm1[w * MROWS + lane] = m1a;  ri1[w * MROWS + lane] = i1a;  rm2[w * MROWS + lane] = m2a;
        rm1[w * MROWS + lane + 32] = m1b;  ri1[w * MROWS + lane + 32] = i1b;  rm2[w * MROWS + lane + 32] = m2b;
        __syncthreads();

        // ---- cross-warp top-2 reduce (threads 0..63, one row each) ----
        if (tid < MROWS) {
            int row = tid;
            float bm1 = INF, bm2 = INF; int bi = 0;
#pragma unroll
            for (int ww = 0; ww < 16; ++ww) {
                float a1 = rm1[ww * MROWS + row];
                int   ai = ri1[ww * MROWS + row];
                float a2 = rm2[ww * MROWS + row];
                if (a1 < bm1 || (a1 == bm1 && ai < bi)) {
                    bm2 = fminf(bm1, a2); bm1 = a1; bi = ai;
                } else {
                    bm2 = fminf(bm2, fminf(a1, a2));
                }
            }
            sbest[row] = bi;
            sflag[row] = (bm2 - bm1 < MARGIN) ? 1 : 0;
        }
        __syncthreads();

        // ---- rare near-tie fallback: exact fp64 re-rank, warp-parallel ----
        for (int row = w; row < MROWS; row += 16) {
            if (!sflag[row]) continue;
            const float* rp = sres + row * RES_PITCH;
            const float* cp = scb + (lane * 8) * DIM;
            double d[8];
#pragma unroll
            for (int e = 0; e < 8; ++e) d[e] = 0.0;
            for (int k = 0; k < DIM; ++k) {
                double rv = (double)rp[k];
#pragma unroll
                for (int e = 0; e < 8; ++e) {
                    double t = rv - (double)cp[e * DIM + k];
                    d[e] = fma(t, t, d[e]);
                }
            }
            double bd = d[0]; int bi = lane * 8;
#pragma unroll
            for (int e = 1; e < 8; ++e)
                if (d[e] < bd) { bd = d[e]; bi = lane * 8 + e; }
#pragma unroll
            for (int off = 16; off > 0; off >>= 1) {
                double od = __shfl_down_sync(0xffffffffu, bd, off);
                int    oi = __shfl_down_sync(0xffffffffu, bi, off);
                if (od < bd || (od == bd && oi < bi)) { bd = od; bi = oi; }
            }
            if (lane == 0) sbest[row] = bi;
        }
        __syncthreads();

        // ---- emit codes; update residual & quantized (fp32, reference op order) ----
        if (codes_out != nullptr && tid < MROWS)
            codes_out[(size_t)lev * NROWS + rowbase + tid] = (float)sbest[tid];
#pragma unroll
        for (int rr = 0; rr < 4; ++rr) {
            int row = w * 4 + rr;
            int be  = sbest[row];
            float4 c  = *(const float4*)(scb + be * DIM + lane * 4);
            float4 rv = *(const float4*)(sres + row * RES_PITCH + lane * 4);
            float4 qv = *(const float4*)(sq   + row * RES_PITCH + lane * 4);
            rv.x -= c.x; rv.y -= c.y; rv.z -= c.z; rv.w -= c.w;
            qv.x += c.x; qv.y += c.y; qv.z += c.z; qv.w += c.w;
            *(float4*)(sres + row * RES_PITCH + lane * 4) = rv;
            *(float4*)(sq   + row * RES_PITCH + lane * 4) = qv;
        }
        __syncthreads();

        // ---- prefetch next level codebook (reuses scb) ----
        if (lev + 1 < NQ) {
            load_cb_async(scb, cbg + (size_t)(lev + 1) * BINS * DIM, tid);
            cp_wait_all();
            __syncthreads();
        }
    }

    // ---- write quantized ----
    if (q_out != nullptr) {
#pragma unroll
        for (int rr = 0; rr < 4; ++rr) {
            int row = w * 4 + rr;
            float4 v = *(const float4*)(sq + row * RES_PITCH + lane * 4);
            *(float4*)(q_out + (size_t)(rowbase + row) * DIM + lane * 4) = v;
        }
    }
}

extern "C" void kernel_launch(void* const* d_in, const int* in_sizes, int n_in,
                              void* d_out, int out_size) {
    const float* hidden = (const float*)d_in[0];
    const float* cb     = (const float*)d_in[1];
    if (n_in >= 2 && in_sizes[0] == NQ * BINS * DIM && in_sizes[1] == NROWS * DIM) {
        // inputs arrived swapped
        const float* t = hidden; hidden = cb; cb = t;
    }

    float* out   = (float*)d_out;
    float* codes = nullptr;
    float* quant = nullptr;
    if (out_size == NQ * NROWS + NROWS * DIM) {        // codes then quantized
        codes = out;
        quant = out + NQ * NROWS;
    } else if (out_size == NROWS * DIM) {              // quantized only
        quant = out;
    } else if (out_size == NQ * NROWS) {               // codes only
        codes = out;
    } else {                                           // default: both, codes first
        codes = out;
        quant = out + NQ * NROWS;
    }

    static int smem_set = 0;
    if (!smem_set) {
        cudaFuncSetAttribute(rvq_kernel,
                             cudaFuncAttributeMaxDynamicSharedMemorySize,
                             SMEM_BYTES);
        smem_set = 1;
    }
    rvq_kernel<<<NCTAS, NTHREADS, SMEM_BYTES>>>(hidden, cb, codes, quant);
}